// round 16
// baseline (speedup 1.0000x reference)
#include <cuda_runtime.h>
#include <cuda_fp16.h>
#include <cstdint>

#define MDIM 1024
#define RANK 128
#define NBATCH 8
#define SEQ 512
#define NROWS (NBATCH * SEQ)          // 4096
#define KSPLIT 4
#define KS (MDIM / KSPLIT)            // 256
#define KC 64                         // k per smem chunk (gemm)
#define CHUNKS (KS / KC)              // 4
#define MTILES (NROWS / 128)          // 32

// Scratch (static __device__ globals; no allocations allowed).
__device__ float g_Tp[KSPLIT][NROWS * RANK];   // K-split partials, 8 MB
__device__ float g_norm[NROWS];                // row squared norms (fp32 exact)
__device__ __half g_Bh[RANK * MDIM];           // B^T: [n][k] fp16
__device__ __half g_Th[NROWS * RANK];          // T: [row][k] fp16
__device__ int g_tick[MTILES];                 // zero-init; reset by combiner

// ---------------- helpers ----------------
__device__ __forceinline__ uint32_t sm2u32(const void* p) {
    uint32_t a;
    asm("{ .reg .u64 t; cvta.to.shared.u64 t, %1; cvt.u32.u64 %0, t; }"
        : "=r"(a) : "l"(p));
    return a;
}
#define LDMX4(r, addr) \
    asm volatile("ldmatrix.sync.aligned.m8n8.x4.shared.b16 {%0,%1,%2,%3}, [%4];" \
        : "=r"((r)[0]), "=r"((r)[1]), "=r"((r)[2]), "=r"((r)[3]) : "r"(addr))

__device__ __forceinline__ void mma_f16(float* c, const uint32_t* a,
                                        uint32_t b0, uint32_t b1) {
    asm volatile(
        "mma.sync.aligned.m16n8k16.row.col.f32.f16.f16.f32 "
        "{%0,%1,%2,%3}, {%4,%5,%6,%7}, {%8,%9}, {%0,%1,%2,%3};"
        : "+f"(c[0]), "+f"(c[1]), "+f"(c[2]), "+f"(c[3])
        : "r"(a[0]), "r"(a[1]), "r"(a[2]), "r"(a[3]), "r"(b0), "r"(b1));
}
#define CP16(dst, src) \
    asm volatile("cp.async.cg.shared.global [%0], [%1], 16;" \
        :: "r"(dst), "l"(src) : "memory")
#define CPCOMMIT() asm volatile("cp.async.commit_group;" ::: "memory")
#define CPWAIT0()  asm volatile("cp.async.wait_group 0;" ::: "memory")
#define CPWAIT1()  asm volatile("cp.async.wait_group 1;" ::: "memory")

// ---------------------------------------------------------------------------
// Kernel 0: transpose proj [1024,128] fp32 -> g_Bh [128][1024] fp16
// ---------------------------------------------------------------------------
__global__ void convertB_kernel(const float* __restrict__ proj)
{
    __shared__ float tile[32][33];
    const int tx = threadIdx.x, ty = threadIdx.y;      // (32,8)
    const int k0 = blockIdx.x * 32, n0 = blockIdx.y * 32;
    #pragma unroll
    for (int i = 0; i < 4; i++)
        tile[ty + 8 * i][tx] = proj[(size_t)(k0 + ty + 8 * i) * RANK + n0 + tx];
    __syncthreads();
    #pragma unroll
    for (int i = 0; i < 4; i++) {
        int n = n0 + ty + 8 * i, k = k0 + tx;
        g_Bh[(size_t)n * MDIM + k] = __float2half_rn(tile[tx][ty + 8 * i]);
    }
}

// ---------------------------------------------------------------------------
// Kernel 1: mma.sync fp16 GEMM with FUSED combine.
// grid (KSPLIT, 32) = 128 CTAs, 512 thr (16 warps). CTA: M=128, N=128,
// K=KS(256) in 4 chunks of 64. Warp grid 4(m)x4(n), warp tile 32x32.
// After writing its partial, the LAST CTA of each m-slab (threadfence +
// counter) sums the 4 partials (L2-hot), emits fp16 T + fp32 norms, and
// resets the counter (deterministic; graph-replay-safe).
// Stage layout (per stage, 36864B): A fp16 [0,18432), Bh [18432,36864).
// ---------------------------------------------------------------------------
#define ST_SZ 36864
#define SMEM_BYTES (2 * ST_SZ)

__global__ void __launch_bounds__(512) mma_gemm_kernel(const float* __restrict__ A)
{
    extern __shared__ char dsm[];
    __shared__ int s_old;
    const int tid  = threadIdx.x;
    const int wid  = tid >> 5, lane = tid & 31;
    const int split = blockIdx.x;
    const int mb    = blockIdx.y * 128;
    const int kbase = split * KS;

    const int warp_m = (wid & 3) * 32;
    const int warp_n = (wid >> 2) * 32;

    const uint32_t smem = sm2u32(dsm);
    const uint32_t a_off = (uint32_t)(warp_m + (lane & 15)) * 144 + (lane >> 4) * 16;
    const uint32_t b_noff = ((lane >> 3) & 1) * 8 + (lane & 7);
    const uint32_t b_off  = (uint32_t)(warp_n + b_noff) * 144 + (lane >> 4) * 16;

    // stage-load indices: A 4 float4/thread (128 rows x 16), B 2 uint4/thread
    int ar[4], ak4[4];
    #pragma unroll
    for (int t = 0; t < 4; t++) { ar[t] = (tid + t * 512) >> 4; ak4[t] = (tid + t * 512) & 15; }
    const int bn[2]  = { (tid + 0) >> 3, (tid + 512) >> 3 };
    const int bg[2]  = { (tid + 0) & 7,  (tid + 512) & 7  };

    float acc[2][4][4];
    #pragma unroll
    for (int mf = 0; mf < 2; mf++)
        #pragma unroll
        for (int i = 0; i < 4; i++)
            #pragma unroll
            for (int j = 0; j < 4; j++) acc[mf][i][j] = 0.0f;

    // ---- prologue: stage chunk 0 into buffer 0 ----
    #pragma unroll
    for (int t = 0; t < 2; t++) {
        size_t src = (size_t)bn[t] * MDIM + kbase + bg[t] * 8;
        CP16(smem + 18432 + bn[t] * 144 + bg[t] * 16, &g_Bh[src]);
    }
    CPCOMMIT();
    #pragma unroll
    for (int t = 0; t < 4; t++) {
        float4 v = *(const float4*)&A[(size_t)(mb + ar[t]) * MDIM + kbase + ak4[t] * 4];
        union { __half2 h2[2]; unsigned long long u; } ph;
        ph.h2[0] = __halves2half2(__float2half_rn(v.x), __float2half_rn(v.y));
        ph.h2[1] = __halves2half2(__float2half_rn(v.z), __float2half_rn(v.w));
        *(unsigned long long*)(dsm + ar[t] * 144 + ak4[t] * 8) = ph.u;
    }
    CPWAIT0();
    __syncthreads();

    for (int c = 0; c < CHUNKS; c++) {
        const uint32_t cur = (uint32_t)(c & 1) * ST_SZ;
        const uint32_t nxt = (uint32_t)((c + 1) & 1) * ST_SZ;

        float4 ra[4];
        if (c + 1 < CHUNKS) {
            const int kn = kbase + (c + 1) * KC;
            #pragma unroll
            for (int t = 0; t < 2; t++) {
                size_t src = (size_t)bn[t] * MDIM + kn + bg[t] * 8;
                CP16(smem + nxt + 18432 + bn[t] * 144 + bg[t] * 16, &g_Bh[src]);
            }
            CPCOMMIT();
            #pragma unroll
            for (int t = 0; t < 4; t++)
                ra[t] = *(const float4*)&A[(size_t)(mb + ar[t]) * MDIM + kn + ak4[t] * 4];
        }

        const uint32_t aaddr = smem + cur + a_off;
        const uint32_t baddr = smem + cur + 18432 + b_off;
        #pragma unroll
        for (int kk = 0; kk < 4; kk++) {
            uint32_t ah[2][4];
            LDMX4(ah[0], aaddr + kk * 32);
            LDMX4(ah[1], aaddr + 16 * 144 + kk * 32);
            #pragma unroll
            for (int nn = 0; nn < 2; nn++) {
                uint32_t bh[4];
                LDMX4(bh, baddr + nn * 16 * 144 + kk * 32);
                #pragma unroll
                for (int mf = 0; mf < 2; mf++) {
                    mma_f16(acc[mf][nn * 2],     ah[mf], bh[0], bh[2]);
                    mma_f16(acc[mf][nn * 2 + 1], ah[mf], bh[1], bh[3]);
                }
            }
        }

        if (c + 1 < CHUNKS) {
            #pragma unroll
            for (int t = 0; t < 4; t++) {
                float4 v = ra[t];
                union { __half2 h2[2]; unsigned long long u; } ph;
                ph.h2[0] = __halves2half2(__float2half_rn(v.x), __float2half_rn(v.y));
                ph.h2[1] = __halves2half2(__float2half_rn(v.z), __float2half_rn(v.w));
                *(unsigned long long*)(dsm + ((c + 1) & 1) * ST_SZ
                                       + ar[t] * 144 + ak4[t] * 8) = ph.u;
            }
            CPWAIT0();
            __syncthreads();
        }
    }

    // ---- write partial ----
    float* __restrict__ P = g_Tp[split];
    #pragma unroll
    for (int mf = 0; mf < 2; mf++) {
        const int m0 = mb + warp_m + mf * 16 + (lane >> 2);
        #pragma unroll
        for (int ch = 0; ch < 4; ch++) {
            int n = warp_n + ch * 8 + (lane & 3) * 2;
            float* a = acc[mf][ch];
            *(float2*)&P[(size_t)m0 * RANK + n] = make_float2(a[0], a[1]);
            *(float2*)&P[(size_t)(m0 + 8) * RANK + n] = make_float2(a[2], a[3]);
        }
    }

    // ---- fused combine: last CTA of this m-slab sums the 4 partials ----
    __threadfence();
    __syncthreads();
    if (tid == 0) s_old = atomicAdd(&g_tick[blockIdx.y], 1);
    __syncthreads();
    if (s_old == KSPLIT - 1) {
        __threadfence();   // acquire: make peers' partial stores visible
        const float4* p0 = (const float4*)g_Tp[0];
        const float4* p1 = (const float4*)g_Tp[1];
        const float4* p2 = (const float4*)g_Tp[2];
        const float4* p3 = (const float4*)g_Tp[3];
        const int base = mb * (RANK / 4);   // float4 index of slab start
        #pragma unroll
        for (int it = 0; it < 8; it++) {
            int idx = base + it * 512 + tid;   // one row per warp (32 f4/row)
            float4 a = p0[idx], b = p1[idx], c = p2[idx], d = p3[idx];
            float4 v;
            v.x = a.x + b.x + c.x + d.x;
            v.y = a.y + b.y + c.y + d.y;
            v.z = a.z + b.z + c.z + d.z;
            v.w = a.w + b.w + c.w + d.w;

            union { __half2 h2[2]; uint2 u; } ph;
            ph.h2[0] = __halves2half2(__float2half_rn(v.x), __float2half_rn(v.y));
            ph.h2[1] = __halves2half2(__float2half_rn(v.z), __float2half_rn(v.w));
            *(uint2*)&g_Th[(size_t)idx * 4] = ph.u;

            float sq = v.x * v.x + v.y * v.y + v.z * v.z + v.w * v.w;
            #pragma unroll
            for (int off = 16; off > 0; off >>= 1)
                sq += __shfl_down_sync(0xffffffffu, sq, off);
            if (lane == 0)
                g_norm[idx >> 5] = sq;
        }
        __syncthreads();
        if (tid == 0) g_tick[blockIdx.y] = 0;   // reset for next graph replay
    }
}

// ---------------------------------------------------------------------------
// Kernel 3: pdist via single-pass fp16 mma.sync Gram (R14 config, unchanged).
// CTA: 128(i) x 128(j) tile, K=128 staged as two cp.async halves. grid (4,4,8),
// 512 thr. Warp grid 4(m)x4(n); warp tile 32x32.
// d(i,j) = n_i + n_j - 2*(I·J); diag forced to 0.
// smem rows 272B; 272 % 128 = 16 -> ldmatrix conflict-free.
// ---------------------------------------------------------------------------
#define PD_I 0
#define PD_J 34816
#define PD_SMEM 69632
#define PD_STR 272

__global__ void __launch_bounds__(512) pdist_mma_kernel(float* __restrict__ out)
{
    extern __shared__ char dsm[];
    const int tid  = threadIdx.x;
    const int wid  = tid >> 5, lane = tid & 31;
    const int bj = blockIdx.x, bi = blockIdx.y, b = blockIdx.z;
    const int i0 = bi * 128, j0 = bj * 128;
    const bool diag = (bi == bj);

    const __half* __restrict__ TH = g_Th + (size_t)b * SEQ * RANK;
    const uint32_t smem = sm2u32(dsm);

    // Stage half 0 (k 0..63), then half 1 (k 64..127), as two cp.async groups.
    #pragma unroll
    for (int h = 0; h < 2; h++) {
        #pragma unroll
        for (int t = 0; t < 2; t++) {
            int idx = tid + t * 512;          // 0..1023
            int r = idx >> 3, g = idx & 7;    // 128 rows x 8 uint4 per half
            uint32_t doff = (uint32_t)r * PD_STR + g * 16 + h * 128;
            size_t soff = (size_t)r * RANK + g * 8 + h * 64;
            CP16(smem + PD_I + doff, TH + (size_t)i0 * RANK + soff);
            if (!diag)
                CP16(smem + PD_J + doff, TH + (size_t)j0 * RANK + soff);
        }
        CPCOMMIT();
    }

    const int warp_m = (wid & 3) * 32;
    const int warp_n = (wid >> 2) * 32;
    const uint32_t ia_off = (uint32_t)(warp_m + (lane & 15)) * PD_STR + (lane >> 4) * 16;
    const uint32_t iaddr = smem + PD_I + ia_off;
    const uint32_t j_noff = ((lane >> 3) & 1) * 8 + (lane & 7);
    const uint32_t ja_off = (uint32_t)(warp_n + j_noff) * PD_STR + (lane >> 4) * 16;
    const uint32_t jaddr = smem + (diag ? PD_I : PD_J) + ja_off;

    float acc[2][4][4];
    #pragma unroll
    for (int mf = 0; mf < 2; mf++)
        #pragma unroll
        for (int i = 0; i < 4; i++)
            #pragma unroll
            for (int j = 0; j < 4; j++) acc[mf][i][j] = 0.0f;

#define PD_MMA_BLOCK(kk) do {                                        \
    uint32_t ih[2][4];                                               \
    LDMX4(ih[0], iaddr + (kk) * 32);                                 \
    LDMX4(ih[1], iaddr + 16 * PD_STR + (kk) * 32);                   \
    _Pragma("unroll")                                                \
    for (int nn = 0; nn < 2; nn++) {                                 \
        uint32_t jh[4];                                              \
        LDMX4(jh, jaddr + nn * 16 * PD_STR + (kk) * 32);             \
        _Pragma("unroll")                                            \
        for (int mf = 0; mf < 2; mf++) {                             \
            mma_f16(acc[mf][nn * 2],     ih[mf], jh[0], jh[2]);      \
            mma_f16(acc[mf][nn * 2 + 1], ih[mf], jh[1], jh[3]);      \
        }                                                            \
    }                                                                \
} while (0)

    CPWAIT1();            // half 0 landed; half 1 still in flight
    __syncthreads();
    #pragma unroll
    for (int kk = 0; kk < 4; kk++) PD_MMA_BLOCK(kk);

    CPWAIT0();            // half 1 landed
    __syncthreads();
    #pragma unroll
    for (int kk = 4; kk < 8; kk++) PD_MMA_BLOCK(kk);
#undef PD_MMA_BLOCK

    // Epilogue: d = n_i + n_j - 2*dot; exact 0 on diagonal.
    const float* __restrict__ nb = g_norm + (size_t)b * SEQ;
    float* __restrict__ ob = out + (size_t)b * SEQ * SEQ;
    #pragma unroll
    for (int mf = 0; mf < 2; mf++) {
        int gi = i0 + warp_m + mf * 16 + (lane >> 2);
        float ni0 = nb[gi], ni1 = nb[gi + 8];
        #pragma unroll
        for (int ch = 0; ch < 4; ch++) {
            int gj = j0 + warp_n + ch * 8 + (lane & 3) * 2;
            float nj0 = nb[gj], nj1 = nb[gj + 1];
            float* a = acc[mf][ch];
            float v00 = ni0 + nj0 - 2.0f * a[0];
            float v01 = ni0 + nj1 - 2.0f * a[1];
            float v10 = ni1 + nj0 - 2.0f * a[2];
            float v11 = ni1 + nj1 - 2.0f * a[3];
            if (diag) {
                if (gi == gj) v00 = 0.0f;
                if (gi == gj + 1) v01 = 0.0f;
                if (gi + 8 == gj) v10 = 0.0f;
                if (gi + 8 == gj + 1) v11 = 0.0f;
            }
            *(float2*)&ob[(size_t)gi * SEQ + gj] = make_float2(v00, v01);
            *(float2*)&ob[(size_t)(gi + 8) * SEQ + gj] = make_float2(v10, v11);
        }
    }
}

extern "C" void kernel_launch(void* const* d_in, const int* in_sizes, int n_in,
                              void* d_out, int out_size)
{
    const float* batch = (const float*)d_in[0];   // [8,512,1024]
    const float* proj  = (const float*)d_in[1];   // [1024,128]
    float* out = (float*)d_out;                   // [8,512,512]

    // Idempotent; first call happens on the correctness run (outside capture).
    cudaFuncSetAttribute(mma_gemm_kernel,
                         cudaFuncAttributeMaxDynamicSharedMemorySize, SMEM_BYTES);
    cudaFuncSetAttribute(pdist_mma_kernel,
                         cudaFuncAttributeMaxDynamicSharedMemorySize, PD_SMEM);

    convertB_kernel<<<dim3(MDIM / 32, RANK / 32), dim3(32, 8)>>>(proj);
    mma_gemm_kernel<<<dim3(KSPLIT, NROWS / 128), 512, SMEM_BYTES>>>(batch);
    pdist_mma_kernel<<<dim3(4, 4, 8), 512, PD_SMEM>>>(out);
}

// round 17
// speedup vs baseline: 1.2284x; 1.2284x over previous
#include <cuda_runtime.h>
#include <cuda_fp16.h>
#include <cstdint>

#define MDIM 1024
#define RANK 128
#define NBATCH 8
#define SEQ 512
#define NROWS (NBATCH * SEQ)          // 4096
#define KSPLIT 4
#define KS (MDIM / KSPLIT)            // 256
#define KC 64                         // k per smem chunk (gemm)
#define CHUNKS (KS / KC)              // 4

// Scratch (static __device__ globals; no allocations allowed).
__device__ float g_Tp[KSPLIT][NROWS * RANK];   // K-split partials, 8 MB
__device__ float g_norm[NROWS];                // row squared norms (fp32 exact)
__device__ __half g_Th[NROWS * RANK];          // T: [row][k] fp16

// ---------------- helpers ----------------
__device__ __forceinline__ uint32_t sm2u32(const void* p) {
    uint32_t a;
    asm("{ .reg .u64 t; cvta.to.shared.u64 t, %1; cvt.u32.u64 %0, t; }"
        : "=r"(a) : "l"(p));
    return a;
}
#define LDMX4(r, addr) \
    asm volatile("ldmatrix.sync.aligned.m8n8.x4.shared.b16 {%0,%1,%2,%3}, [%4];" \
        : "=r"((r)[0]), "=r"((r)[1]), "=r"((r)[2]), "=r"((r)[3]) : "r"(addr))
#define LDMX4T(r, addr) \
    asm volatile("ldmatrix.sync.aligned.m8n8.x4.trans.shared.b16 {%0,%1,%2,%3}, [%4];" \
        : "=r"((r)[0]), "=r"((r)[1]), "=r"((r)[2]), "=r"((r)[3]) : "r"(addr))

__device__ __forceinline__ void mma_f16(float* c, const uint32_t* a,
                                        uint32_t b0, uint32_t b1) {
    asm volatile(
        "mma.sync.aligned.m16n8k16.row.col.f32.f16.f16.f32 "
        "{%0,%1,%2,%3}, {%4,%5,%6,%7}, {%8,%9}, {%0,%1,%2,%3};"
        : "+f"(c[0]), "+f"(c[1]), "+f"(c[2]), "+f"(c[3])
        : "r"(a[0]), "r"(a[1]), "r"(a[2]), "r"(a[3]), "r"(b0), "r"(b1));
}
#define CP16(dst, src) \
    asm volatile("cp.async.cg.shared.global [%0], [%1], 16;" \
        :: "r"(dst), "l"(src) : "memory")
#define CPCOMMIT() asm volatile("cp.async.commit_group;" ::: "memory")
#define CPWAIT0()  asm volatile("cp.async.wait_group 0;" ::: "memory")
#define CPWAIT1()  asm volatile("cp.async.wait_group 1;" ::: "memory")

// ---------------------------------------------------------------------------
// Kernel 1: mma.sync fp16 GEMM, B consumed directly from proj[k][n] fp32 via
// in-kernel fp32->fp16 convert (no transpose) + ldmatrix.trans fragments.
// grid (KSPLIT, 32) = 128 CTAs, 512 thr (16 warps). CTA: M=128, N=128,
// K=KS(256) in 4 chunks of 64. Warp grid 4(m)x4(n), warp tile 32x32.
// Stage layout (per stage, 35840B):
//   A fp16 [0,18432): 128 rows x 144B (k-contig rows)
//   B fp16 [18432,35840): 64 k-rows x 272B (n-contig rows; 272%128=16 ->
//   conflict-free ldmatrix)
// ---------------------------------------------------------------------------
#define B_OFF 18432
#define ST_SZ 35840
#define SMEM_BYTES (2 * ST_SZ)

__global__ void __launch_bounds__(512) mma_gemm_kernel(const float* __restrict__ A,
                                                       const float* __restrict__ Bp)
{
    extern __shared__ char dsm[];
    const int tid  = threadIdx.x;
    const int wid  = tid >> 5, lane = tid & 31;
    const int split = blockIdx.x;
    const int mb    = blockIdx.y * 128;
    const int kbase = split * KS;

    const int warp_m = (wid & 3) * 32;
    const int warp_n = (wid >> 2) * 32;

    const uint32_t smem = sm2u32(dsm);
    const uint32_t a_off = (uint32_t)(warp_m + (lane & 15)) * 144 + (lane >> 4) * 16;
    // B ldmatrix.trans lane address: k-row = (lane>>4)*8 + (lane&7),
    // n column base = warp_n + ((lane>>3)&1)*8.
    const uint32_t b_off = (uint32_t)(((lane >> 4) * 8) + (lane & 7)) * 272
                         + (uint32_t)(warp_n + (((lane >> 3) & 1) * 8)) * 2;

    // stage-load indices: A 4 float4/thread (128 rows x 16 f4),
    // B 4 float4/thread (64 k-rows x 32 f4).
    int ar[4], ak4[4], bk[4], bn4[4];
    #pragma unroll
    for (int t = 0; t < 4; t++) {
        int ia = tid + t * 512;
        ar[t]  = ia >> 4;  ak4[t] = ia & 15;
        bk[t]  = ia >> 5;  bn4[t] = ia & 31;
    }

    float acc[2][4][4];
    #pragma unroll
    for (int mf = 0; mf < 2; mf++)
        #pragma unroll
        for (int i = 0; i < 4; i++)
            #pragma unroll
            for (int j = 0; j < 4; j++) acc[mf][i][j] = 0.0f;

    // convert+store a float4 as 4 fp16 (8B) into smem
#define CVT_STORE(off, v) do {                                               \
        union { __half2 h2[2]; unsigned long long u; } _p;                   \
        _p.h2[0] = __halves2half2(__float2half_rn((v).x), __float2half_rn((v).y)); \
        _p.h2[1] = __halves2half2(__float2half_rn((v).z), __float2half_rn((v).w)); \
        *(unsigned long long*)(dsm + (off)) = _p.u;                          \
    } while (0)

    // ---- prologue: stage chunk 0 into buffer 0 ----
    #pragma unroll
    for (int t = 0; t < 4; t++) {
        float4 va = *(const float4*)&A[(size_t)(mb + ar[t]) * MDIM + kbase + ak4[t] * 4];
        CVT_STORE(ar[t] * 144 + ak4[t] * 8, va);
        float4 vb = *(const float4*)&Bp[(size_t)(kbase + bk[t]) * RANK + bn4[t] * 4];
        CVT_STORE(B_OFF + bk[t] * 272 + bn4[t] * 8, vb);
    }
    __syncthreads();

    for (int c = 0; c < CHUNKS; c++) {
        const uint32_t cur = (uint32_t)(c & 1) * ST_SZ;
        const uint32_t nxtb = (uint32_t)((c + 1) & 1) * ST_SZ;

        float4 ra[4], rb[4];
        if (c + 1 < CHUNKS) {
            const int kn = kbase + (c + 1) * KC;
            #pragma unroll
            for (int t = 0; t < 4; t++) {
                ra[t] = *(const float4*)&A[(size_t)(mb + ar[t]) * MDIM + kn + ak4[t] * 4];
                rb[t] = *(const float4*)&Bp[(size_t)(kn + bk[t]) * RANK + bn4[t] * 4];
            }
        }

        const uint32_t aaddr = smem + cur + a_off;
        const uint32_t baddr = smem + cur + B_OFF + b_off;
        #pragma unroll
        for (int kk = 0; kk < 4; kk++) {
            uint32_t ah[2][4];
            LDMX4(ah[0], aaddr + kk * 32);
            LDMX4(ah[1], aaddr + 16 * 144 + kk * 32);
            #pragma unroll
            for (int nn = 0; nn < 2; nn++) {
                uint32_t bh[4];
                LDMX4T(bh, baddr + kk * 16 * 272 + nn * 16 * 2);
                #pragma unroll
                for (int mf = 0; mf < 2; mf++) {
                    mma_f16(acc[mf][nn * 2],     ah[mf], bh[0], bh[2]);
                    mma_f16(acc[mf][nn * 2 + 1], ah[mf], bh[1], bh[3]);
                }
            }
        }

        if (c + 1 < CHUNKS) {
            __syncthreads();   // everyone done reading next buffer's old data
            #pragma unroll
            for (int t = 0; t < 4; t++) {
                CVT_STORE(nxtb + ar[t] * 144 + ak4[t] * 8, ra[t]);
                CVT_STORE(nxtb + B_OFF + bk[t] * 272 + bn4[t] * 8, rb[t]);
            }
            __syncthreads();
        }
    }
#undef CVT_STORE

    float* __restrict__ P = g_Tp[split];
    #pragma unroll
    for (int mf = 0; mf < 2; mf++) {
        const int m0 = mb + warp_m + mf * 16 + (lane >> 2);
        #pragma unroll
        for (int ch = 0; ch < 4; ch++) {
            int n = warp_n + ch * 8 + (lane & 3) * 2;
            float* a = acc[mf][ch];
            *(float2*)&P[(size_t)m0 * RANK + n] = make_float2(a[0], a[1]);
            *(float2*)&P[(size_t)(m0 + 8) * RANK + n] = make_float2(a[2], a[3]);
        }
    }
}

// ---------------------------------------------------------------------------
// Kernel 2: combine 4 K-split partials -> fp16 T + fp32 per-row squared norms.
// ---------------------------------------------------------------------------
__global__ void __launch_bounds__(256) combine_kernel()
{
    int idx = blockIdx.x * 256 + threadIdx.x;      // float4 index
    const float4* p0 = (const float4*)g_Tp[0];
    const float4* p1 = (const float4*)g_Tp[1];
    const float4* p2 = (const float4*)g_Tp[2];
    const float4* p3 = (const float4*)g_Tp[3];
    float4 a = p0[idx], b = p1[idx], c = p2[idx], d = p3[idx];
    float4 v;
    v.x = a.x + b.x + c.x + d.x;
    v.y = a.y + b.y + c.y + d.y;
    v.z = a.z + b.z + c.z + d.z;
    v.w = a.w + b.w + c.w + d.w;

    union { __half2 h2[2]; uint2 u; } ph;
    ph.h2[0] = __halves2half2(__float2half_rn(v.x), __float2half_rn(v.y));
    ph.h2[1] = __halves2half2(__float2half_rn(v.z), __float2half_rn(v.w));
    *(uint2*)&g_Th[(size_t)idx * 4] = ph.u;

    float sq = v.x * v.x + v.y * v.y + v.z * v.z + v.w * v.w;
    #pragma unroll
    for (int off = 16; off > 0; off >>= 1)
        sq += __shfl_down_sync(0xffffffffu, sq, off);
    if ((threadIdx.x & 31) == 0)
        g_norm[idx >> 5] = sq;                     // 32 float4 per row
}

// ---------------------------------------------------------------------------
// Kernel 3: pdist via single-pass fp16 mma.sync Gram (R14 config, unchanged).
// CTA: 128(i) x 128(j) tile, K=128 staged as two cp.async halves. grid (4,4,8),
// 512 thr. Warp grid 4(m)x4(n); warp tile 32x32.
// d(i,j) = n_i + n_j - 2*(I·J); diag forced to 0.
// smem rows 272B; 272 % 128 = 16 -> ldmatrix conflict-free.
// ---------------------------------------------------------------------------
#define PD_I 0
#define PD_J 34816
#define PD_SMEM 69632
#define PD_STR 272

__global__ void __launch_bounds__(512) pdist_mma_kernel(float* __restrict__ out)
{
    extern __shared__ char dsm[];
    const int tid  = threadIdx.x;
    const int wid  = tid >> 5, lane = tid & 31;
    const int bj = blockIdx.x, bi = blockIdx.y, b = blockIdx.z;
    const int i0 = bi * 128, j0 = bj * 128;
    const bool diag = (bi == bj);

    const __half* __restrict__ TH = g_Th + (size_t)b * SEQ * RANK;
    const uint32_t smem = sm2u32(dsm);

    // Stage half 0 (k 0..63), then half 1 (k 64..127), as two cp.async groups.
    #pragma unroll
    for (int h = 0; h < 2; h++) {
        #pragma unroll
        for (int t = 0; t < 2; t++) {
            int idx = tid + t * 512;          // 0..1023
            int r = idx >> 3, g = idx & 7;    // 128 rows x 8 uint4 per half
            uint32_t doff = (uint32_t)r * PD_STR + g * 16 + h * 128;
            size_t soff = (size_t)r * RANK + g * 8 + h * 64;
            CP16(smem + PD_I + doff, TH + (size_t)i0 * RANK + soff);
            if (!diag)
                CP16(smem + PD_J + doff, TH + (size_t)j0 * RANK + soff);
        }
        CPCOMMIT();
    }

    const int warp_m = (wid & 3) * 32;
    const int warp_n = (wid >> 2) * 32;
    const uint32_t ia_off = (uint32_t)(warp_m + (lane & 15)) * PD_STR + (lane >> 4) * 16;
    const uint32_t iaddr = smem + PD_I + ia_off;
    const uint32_t j_noff = ((lane >> 3) & 1) * 8 + (lane & 7);
    const uint32_t ja_off = (uint32_t)(warp_n + j_noff) * PD_STR + (lane >> 4) * 16;
    const uint32_t jaddr = smem + (diag ? PD_I : PD_J) + ja_off;

    float acc[2][4][4];
    #pragma unroll
    for (int mf = 0; mf < 2; mf++)
        #pragma unroll
        for (int i = 0; i < 4; i++)
            #pragma unroll
            for (int j = 0; j < 4; j++) acc[mf][i][j] = 0.0f;

#define PD_MMA_BLOCK(kk) do {                                        \
    uint32_t ih[2][4];                                               \
    LDMX4(ih[0], iaddr + (kk) * 32);                                 \
    LDMX4(ih[1], iaddr + 16 * PD_STR + (kk) * 32);                   \
    _Pragma("unroll")                                                \
    for (int nn = 0; nn < 2; nn++) {                                 \
        uint32_t jh[4];                                              \
        LDMX4(jh, jaddr + nn * 16 * PD_STR + (kk) * 32);             \
        _Pragma("unroll")                                            \
        for (int mf = 0; mf < 2; mf++) {                             \
            mma_f16(acc[mf][nn * 2],     ih[mf], jh[0], jh[2]);      \
            mma_f16(acc[mf][nn * 2 + 1], ih[mf], jh[1], jh[3]);      \
        }                                                            \
    }                                                                \
} while (0)

    CPWAIT1();            // half 0 landed; half 1 still in flight
    __syncthreads();
    #pragma unroll
    for (int kk = 0; kk < 4; kk++) PD_MMA_BLOCK(kk);

    CPWAIT0();            // half 1 landed
    __syncthreads();
    #pragma unroll
    for (int kk = 4; kk < 8; kk++) PD_MMA_BLOCK(kk);
#undef PD_MMA_BLOCK

    // Epilogue: d = n_i + n_j - 2*dot; exact 0 on diagonal.
    const float* __restrict__ nb = g_norm + (size_t)b * SEQ;
    float* __restrict__ ob = out + (size_t)b * SEQ * SEQ;
    #pragma unroll
    for (int mf = 0; mf < 2; mf++) {
        int gi = i0 + warp_m + mf * 16 + (lane >> 2);
        float ni0 = nb[gi], ni1 = nb[gi + 8];
        #pragma unroll
        for (int ch = 0; ch < 4; ch++) {
            int gj = j0 + warp_n + ch * 8 + (lane & 3) * 2;
            float nj0 = nb[gj], nj1 = nb[gj + 1];
            float* a = acc[mf][ch];
            float v00 = ni0 + nj0 - 2.0f * a[0];
            float v01 = ni0 + nj1 - 2.0f * a[1];
            float v10 = ni1 + nj0 - 2.0f * a[2];
            float v11 = ni1 + nj1 - 2.0f * a[3];
            if (diag) {
                if (gi == gj) v00 = 0.0f;
                if (gi == gj + 1) v01 = 0.0f;
                if (gi + 8 == gj) v10 = 0.0f;
                if (gi + 8 == gj + 1) v11 = 0.0f;
            }
            *(float2*)&ob[(size_t)gi * SEQ + gj] = make_float2(v00, v01);
            *(float2*)&ob[(size_t)(gi + 8) * SEQ + gj] = make_float2(v10, v11);
        }
    }
}

extern "C" void kernel_launch(void* const* d_in, const int* in_sizes, int n_in,
                              void* d_out, int out_size)
{
    const float* batch = (const float*)d_in[0];   // [8,512,1024]
    const float* proj  = (const float*)d_in[1];   // [1024,128]
    float* out = (float*)d_out;                   // [8,512,512]

    // Idempotent; first call happens on the correctness run (outside capture).
    cudaFuncSetAttribute(mma_gemm_kernel,
                         cudaFuncAttributeMaxDynamicSharedMemorySize, SMEM_BYTES);
    cudaFuncSetAttribute(pdist_mma_kernel,
                         cudaFuncAttributeMaxDynamicSharedMemorySize, PD_SMEM);

    mma_gemm_kernel<<<dim3(KSPLIT, NROWS / 128), 512, SMEM_BYTES>>>(batch, proj);
    combine_kernel<<<NROWS * RANK / 4 / 256, 256>>>();
    pdist_mma_kernel<<<dim3(4, 4, 8), 512, PD_SMEM>>>(out);
}